// round 7
// baseline (speedup 1.0000x reference)
#include <cuda_runtime.h>
#include <cstdint>

// ============================================================================
// GroupedExperts: out = (silu(x@gate) * (x@up)) @ down, per expert.
// 8 experts x 2048 tokens, DIM=2048, HIDDEN=5632, fp32.
// Build target is plain sm_103 (no 'a' features!) => tcgen05/TMA unavailable.
// Path: mma.sync.m16n8k8 tf32 (cvt.rna), cp.async 3-stage ring, no transposes,
// silu fused into the up-GEMM epilogue.
// ============================================================================

#define NE    8
#define DIMX  2048
#define HID   5632
#define TPE   2048
#define NTOK  (NE * TPE)

// device scratch (no allocation allowed)
__device__ __align__(256) float g_g[(size_t)NTOK * HID];  // x@gate
__device__ __align__(256) float g_h[(size_t)NTOK * HID];  // silu(g)*(x@up)

// ---- helpers ---------------------------------------------------------------
__device__ __forceinline__ uint32_t sptr(const void* p) {
    uint32_t a;
    asm("{ .reg .u64 t; cvta.to.shared.u64 t, %1; cvt.u32.u64 %0, t; }"
        : "=r"(a) : "l"(p));
    return a;
}
__device__ __forceinline__ void cp16(uint32_t s, const void* g) {
    asm volatile("cp.async.cg.shared.global [%0], [%1], 16;"
                 :: "r"(s), "l"(g) : "memory");
}
__device__ __forceinline__ uint32_t f2tf(float f) {
    uint32_t r;
    asm("cvt.rna.tf32.f32 %0, %1;" : "=r"(r) : "f"(f));
    return r;
}
__device__ __forceinline__ void mma8(float* d, const uint32_t* a,
                                     uint32_t b0, uint32_t b1) {
    asm volatile(
        "mma.sync.aligned.m16n8k8.row.col.f32.tf32.tf32.f32 "
        "{%0,%1,%2,%3}, {%4,%5,%6,%7}, {%8,%9}, {%0,%1,%2,%3};"
        : "+f"(d[0]), "+f"(d[1]), "+f"(d[2]), "+f"(d[3])
        : "r"(a[0]), "r"(a[1]), "r"(a[2]), "r"(a[3]), "r"(b0), "r"(b1));
}

// ---- GEMM config -----------------------------------------------------------
// CTA tile 128(M) x 128(N) x 32(K-chunk); 256 threads, warp grid 4M x 2N,
// warp tile 32x64.  A smem [128][36] (pad for conflict-free quad access),
// B smem [32][136] (weights staged as-is: K rows, N contiguous).
#define STAGES   3
#define APITCH   36
#define BPITCH   136
#define A_TILE_F (128 * APITCH)              // 4608 floats
#define B_TILE_F (32 * BPITCH)               // 4352 floats
#define STAGE_F  (A_TILE_F + B_TILE_F)       // 8960 floats = 35840 B
#define SMEM_SZ  (STAGES * STAGE_F * 4)      // 107520 B

// EPI 0: C = acc.  EPI 1: C = silu(G) * acc  (G read at same coords).
template<int EPI>
__global__ void __launch_bounds__(256, 2) moe_mma(
    const float* __restrict__ A, const float* __restrict__ B,
    const float* __restrict__ G, float* __restrict__ C,
    int K, int Nw)
{
    extern __shared__ float sm[];
    const uint32_t smb = sptr(sm);
    const int tid = threadIdx.x, lid = tid & 31, wid = tid >> 5;
    const int wm = (wid & 3) << 5;            // warp M offset (0..96)
    const int wn = (wid >> 2) << 6;           // warp N offset (0 or 64)
    const int nb = blockIdx.x << 7;
    const int mb = blockIdx.y << 7;
    const int e  = mb / TPE;                  // 16 M-tiles per expert, exact
    const float* Ab = A + (size_t)mb * K;
    const float* Bb = B + (size_t)e * K * Nw + nb;
    const int NK = K >> 5;

    float acc[2][8][4];
    #pragma unroll
    for (int mi = 0; mi < 2; mi++)
        #pragma unroll
        for (int ni = 0; ni < 8; ni++)
            #pragma unroll
            for (int q = 0; q < 4; q++) acc[mi][ni][q] = 0.f;

    auto load = [&](int kc, int s) {
        const uint32_t sA = smb + (uint32_t)(s * STAGE_F) * 4;
        const uint32_t sB = sA + A_TILE_F * 4;
        const float* gA = Ab + kc * 32;
        const float* gB = Bb + (size_t)(kc * 32) * Nw;
        #pragma unroll
        for (int i = 0; i < 4; i++) {          // A: 128 rows x 32 floats
            int idx = tid + (i << 8); int r = idx >> 3, j = idx & 7;
            cp16(sA + (uint32_t)(r * APITCH + (j << 2)) * 4,
                 gA + (size_t)r * K + (j << 2));
        }
        #pragma unroll
        for (int i = 0; i < 4; i++) {          // B: 32 rows x 128 floats
            int idx = tid + (i << 8); int r = idx >> 5, j = idx & 31;
            cp16(sB + (uint32_t)(r * BPITCH + (j << 2)) * 4,
                 gB + (size_t)r * Nw + (j << 2));
        }
    };

    load(0, 0); asm volatile("cp.async.commit_group;" ::: "memory");
    load(1, 1); asm volatile("cp.async.commit_group;" ::: "memory");
    load(2, 2); asm volatile("cp.async.commit_group;" ::: "memory");

    int s = 0;
    #pragma unroll 1
    for (int kc = 0; kc < NK; kc++) {
        asm volatile("cp.async.wait_group 2;" ::: "memory");
        __syncthreads();

        const float* sA = sm + s * STAGE_F;
        const float* sB = sA + A_TILE_F;
        const int l4 = lid >> 2, lm = lid & 3;

        #pragma unroll
        for (int ks = 0; ks < 4; ks++) {
            const int k0 = ks << 3;
            uint32_t af[2][4];
            #pragma unroll
            for (int mi = 0; mi < 2; mi++) {
                const int rb = wm + (mi << 4) + l4;
                const int c  = k0 + lm;
                af[mi][0] = f2tf(sA[rb * APITCH + c]);
                af[mi][1] = f2tf(sA[(rb + 8) * APITCH + c]);
                af[mi][2] = f2tf(sA[rb * APITCH + c + 4]);
                af[mi][3] = f2tf(sA[(rb + 8) * APITCH + c + 4]);
            }
            #pragma unroll
            for (int ni = 0; ni < 8; ni++) {
                const int cb = wn + (ni << 3) + l4;
                const int kr = k0 + lm;
                uint32_t b0 = f2tf(sB[kr * BPITCH + cb]);
                uint32_t b1 = f2tf(sB[(kr + 4) * BPITCH + cb]);
                mma8(acc[0][ni], af[0], b0, b1);
                mma8(acc[1][ni], af[1], b0, b1);
            }
        }
        __syncthreads();
        if (kc + STAGES < NK) load(kc + STAGES, s);
        asm volatile("cp.async.commit_group;" ::: "memory");  // keep count fixed
        s = (s + 1 == STAGES) ? 0 : s + 1;
    }

    // ---- epilogue ----
    const int l4 = lid >> 2, lm = lid & 3;
    #pragma unroll
    for (int mi = 0; mi < 2; mi++) {
        #pragma unroll
        for (int h2 = 0; h2 < 2; h2++) {
            const int r = mb + wm + (mi << 4) + (h2 << 3) + l4;
            const size_t off = (size_t)r * Nw + nb + wn + (lm << 1);
            float* Cr = C + off;
            #pragma unroll
            for (int ni = 0; ni < 8; ni++) {
                float c0 = acc[mi][ni][h2 * 2 + 0];
                float c1 = acc[mi][ni][h2 * 2 + 1];
                if (EPI) {
                    float2 g = *(const float2*)(G + off + (ni << 3));
                    c0 *= g.x / (1.f + __expf(-g.x));
                    c1 *= g.y / (1.f + __expf(-g.y));
                }
                *(float2*)(Cr + (ni << 3)) = make_float2(c0, c1);
            }
        }
    }
}

// ---- launch ----------------------------------------------------------------
extern "C" void kernel_launch(void* const* d_in, const int* in_sizes, int n_in,
                              void* d_out, int out_size) {
    (void)in_sizes; (void)n_in; (void)out_size;
    const float* x    = (const float*)d_in[0];
    const float* gate = (const float*)d_in[1];
    const float* up   = (const float*)d_in[2];
    const float* down = (const float*)d_in[3];
    float* out = (float*)d_out;

    void *pg, *ph;
    cudaGetSymbolAddress(&pg, g_g);
    cudaGetSymbolAddress(&ph, g_h);

    static bool attr_done = false;
    cudaFuncSetAttribute(moe_mma<0>, cudaFuncAttributeMaxDynamicSharedMemorySize, SMEM_SZ);
    cudaFuncSetAttribute(moe_mma<1>, cudaFuncAttributeMaxDynamicSharedMemorySize, SMEM_SZ);
    (void)attr_done;

    // g = x @ gate
    moe_mma<0><<<dim3(HID / 128, NTOK / 128), 256, SMEM_SZ>>>(
        x, gate, nullptr, (float*)pg, DIMX, HID);
    // h = silu(g) * (x @ up)
    moe_mma<1><<<dim3(HID / 128, NTOK / 128), 256, SMEM_SZ>>>(
        x, up, (const float*)pg, (float*)ph, DIMX, HID);
    // out = h @ down
    moe_mma<0><<<dim3(DIMX / 128, NTOK / 128), 256, SMEM_SZ>>>(
        (const float*)ph, down, nullptr, out, HID, DIMX);
}

// round 8
// speedup vs baseline: 1.0929x; 1.0929x over previous
#include <cuda_runtime.h>
#include <cstdint>

// ============================================================================
// GroupedExperts: out = (silu(x@gate) * (x@up)) @ down, per expert.
// 8 experts x 2048 tokens, DIM=2048, HIDDEN=5632, fp32.
// Target is plain sm_103 (no 'a' features) => mma.sync m16n8k8 tf32 path.
// R7: pre-round operands to tf32 once (kills per-use cvt), fuse gate+up
// (kills g roundtrip), keep proven cp.async skeleton.
// ============================================================================

#define NE    8
#define DIMX  2048
#define HID   5632
#define TPE   2048
#define NTOK  (NE * TPE)

// device scratch (no allocation allowed)
__device__ __align__(256) float g_xc[(size_t)NTOK * DIMX];     // tf32-rounded x
__device__ __align__(256) float g_gc[(size_t)NE * DIMX * HID]; // tf32 gate
__device__ __align__(256) float g_uc[(size_t)NE * DIMX * HID]; // tf32 up
__device__ __align__(256) float g_dc[(size_t)NE * HID * DIMX]; // tf32 down
__device__ __align__(256) float g_h [(size_t)NTOK * HID];      // tf32 h

// ---- helpers ---------------------------------------------------------------
__device__ __forceinline__ uint32_t sptr(const void* p) {
    uint32_t a;
    asm("{ .reg .u64 t; cvta.to.shared.u64 t, %1; cvt.u32.u64 %0, t; }"
        : "=r"(a) : "l"(p));
    return a;
}
__device__ __forceinline__ void cp16(uint32_t s, const void* g) {
    asm volatile("cp.async.cg.shared.global [%0], [%1], 16;"
                 :: "r"(s), "l"(g) : "memory");
}
__device__ __forceinline__ float rna(float f) {
    uint32_t r;
    asm("cvt.rna.tf32.f32 %0, %1;" : "=r"(r) : "f"(f));
    return __uint_as_float(r);
}
__device__ __forceinline__ void mma8(float* d, const uint32_t* a,
                                     uint32_t b0, uint32_t b1) {
    asm volatile(
        "mma.sync.aligned.m16n8k8.row.col.f32.tf32.tf32.f32 "
        "{%0,%1,%2,%3}, {%4,%5,%6,%7}, {%8,%9}, {%0,%1,%2,%3};"
        : "+f"(d[0]), "+f"(d[1]), "+f"(d[2]), "+f"(d[3])
        : "r"(a[0]), "r"(a[1]), "r"(a[2]), "r"(a[3]), "r"(b0), "r"(b1));
}

// ---- tf32 pre-round pass ---------------------------------------------------
__global__ void cvt_tf32(const float4* __restrict__ in, float4* __restrict__ out,
                         size_t n4) {
    size_t i = (size_t)blockIdx.x * blockDim.x + threadIdx.x;
    const size_t stride = (size_t)gridDim.x * blockDim.x;
    for (; i < n4; i += stride) {
        float4 v = in[i];
        v.x = rna(v.x); v.y = rna(v.y); v.z = rna(v.z); v.w = rna(v.w);
        out[i] = v;
    }
}

// ---- GEMM config -----------------------------------------------------------
// CTA tile 128(M) x 128(N) x 32(K-chunk); 256 threads, warp grid 4M x 2N,
// warp tile 32x64. A smem [128][36], B smem [32][136] (conflict-free pitches).
// NB=2: second B matrix (up) shares the A tile; two accumulator sets.
#define STAGES   3
#define APITCH   36
#define BPITCH   136
#define A_TILE_F (128 * APITCH)              // 4608 floats
#define B_TILE_F (32 * BPITCH)               // 4352 floats

template<int NB> struct Cfg {
    static const int STAGE_F = A_TILE_F + NB * B_TILE_F;
    static const int SMEM_SZ = STAGES * STAGE_F * 4;
};

// EPI 0: C = accG.   EPI 1: C = rna( silu(accG) * accU ).
template<int NB, int EPI>
__global__ void __launch_bounds__(256, (NB == 1 ? 2 : 1)) moe_mma(
    const float* __restrict__ A, const float* __restrict__ B0,
    const float* __restrict__ B1, float* __restrict__ C,
    int K, int Nw)
{
    extern __shared__ float sm[];
    const uint32_t smb = sptr(sm);
    const int tid = threadIdx.x, lid = tid & 31, wid = tid >> 5;
    const int wm = (wid & 3) << 5;            // warp M offset
    const int wn = (wid >> 2) << 6;           // warp N offset
    const int nb = blockIdx.x << 7;
    const int mb = blockIdx.y << 7;
    const int e  = mb / TPE;
    const float* Ab  = A  + (size_t)mb * K;
    const float* B0b = B0 + (size_t)e * K * Nw + nb;
    const float* B1b = (NB == 2) ? (B1 + (size_t)e * K * Nw + nb) : B0b;
    const int NK = K >> 5;
    const int STAGE_F = Cfg<NB>::STAGE_F;

    float accG[2][8][4];
    float accU[2][8][4];
    #pragma unroll
    for (int mi = 0; mi < 2; mi++)
        #pragma unroll
        for (int ni = 0; ni < 8; ni++)
            #pragma unroll
            for (int q = 0; q < 4; q++) {
                accG[mi][ni][q] = 0.f;
                if (NB == 2) accU[mi][ni][q] = 0.f;
            }

    auto load = [&](int kc, int s) {
        const uint32_t sA  = smb + (uint32_t)(s * STAGE_F) * 4;
        const uint32_t sB0 = sA + A_TILE_F * 4;
        const float* gA  = Ab  + kc * 32;
        const float* gB0 = B0b + (size_t)(kc * 32) * Nw;
        #pragma unroll
        for (int i = 0; i < 4; i++) {          // A: 128 rows x 32 floats
            int idx = tid + (i << 8); int r = idx >> 3, j = idx & 7;
            cp16(sA + (uint32_t)(r * APITCH + (j << 2)) * 4,
                 gA + (size_t)r * K + (j << 2));
        }
        #pragma unroll
        for (int i = 0; i < 4; i++) {          // B0: 32 rows x 128 floats
            int idx = tid + (i << 8); int r = idx >> 5, j = idx & 31;
            cp16(sB0 + (uint32_t)(r * BPITCH + (j << 2)) * 4,
                 gB0 + (size_t)r * Nw + (j << 2));
        }
        if (NB == 2) {
            const uint32_t sB1 = sB0 + B_TILE_F * 4;
            const float* gB1 = B1b + (size_t)(kc * 32) * Nw;
            #pragma unroll
            for (int i = 0; i < 4; i++) {
                int idx = tid + (i << 8); int r = idx >> 5, j = idx & 31;
                cp16(sB1 + (uint32_t)(r * BPITCH + (j << 2)) * 4,
                     gB1 + (size_t)r * Nw + (j << 2));
            }
        }
    };

    load(0, 0); asm volatile("cp.async.commit_group;" ::: "memory");
    load(1, 1); asm volatile("cp.async.commit_group;" ::: "memory");
    load(2, 2); asm volatile("cp.async.commit_group;" ::: "memory");

    int s = 0;
    const int l4 = lid >> 2, lm = lid & 3;
    #pragma unroll 1
    for (int kc = 0; kc < NK; kc++) {
        asm volatile("cp.async.wait_group 2;" ::: "memory");
        __syncthreads();

        const float* sA  = sm + s * STAGE_F;
        const float* sB0 = sA + A_TILE_F;
        const float* sB1 = sB0 + B_TILE_F;

        #pragma unroll
        for (int ks = 0; ks < 4; ks++) {
            const int k0 = ks << 3;
            uint32_t af[2][4];
            #pragma unroll
            for (int mi = 0; mi < 2; mi++) {
                const int rb = wm + (mi << 4) + l4;
                const int c  = k0 + lm;
                af[mi][0] = __float_as_uint(sA[rb * APITCH + c]);
                af[mi][1] = __float_as_uint(sA[(rb + 8) * APITCH + c]);
                af[mi][2] = __float_as_uint(sA[rb * APITCH + c + 4]);
                af[mi][3] = __float_as_uint(sA[(rb + 8) * APITCH + c + 4]);
            }
            #pragma unroll
            for (int ni = 0; ni < 8; ni++) {
                const int cb = wn + (ni << 3) + l4;
                const int kr = k0 + lm;
                uint32_t b0 = __float_as_uint(sB0[kr * BPITCH + cb]);
                uint32_t b1 = __float_as_uint(sB0[(kr + 4) * BPITCH + cb]);
                mma8(accG[0][ni], af[0], b0, b1);
                mma8(accG[1][ni], af[1], b0, b1);
                if (NB == 2) {
                    uint32_t u0 = __float_as_uint(sB1[kr * BPITCH + cb]);
                    uint32_t u1 = __float_as_uint(sB1[(kr + 4) * BPITCH + cb]);
                    mma8(accU[0][ni], af[0], u0, u1);
                    mma8(accU[1][ni], af[1], u0, u1);
                }
            }
        }
        __syncthreads();
        if (kc + STAGES < NK) load(kc + STAGES, s);
        asm volatile("cp.async.commit_group;" ::: "memory");  // fixed cadence
        s = (s + 1 == STAGES) ? 0 : s + 1;
    }

    // ---- epilogue ----
    #pragma unroll
    for (int mi = 0; mi < 2; mi++) {
        #pragma unroll
        for (int h2 = 0; h2 < 2; h2++) {
            const int r = mb + wm + (mi << 4) + (h2 << 3) + l4;
            float* Cr = C + (size_t)r * Nw + nb + wn + (lm << 1);
            #pragma unroll
            for (int ni = 0; ni < 8; ni++) {
                float c0 = accG[mi][ni][h2 * 2 + 0];
                float c1 = accG[mi][ni][h2 * 2 + 1];
                if (EPI) {
                    float u0 = accU[mi][ni][h2 * 2 + 0];
                    float u1 = accU[mi][ni][h2 * 2 + 1];
                    c0 = rna(u0 * (c0 / (1.f + __expf(-c0))));
                    c1 = rna(u1 * (c1 / (1.f + __expf(-c1))));
                }
                *(float2*)(Cr + (ni << 3)) = make_float2(c0, c1);
            }
        }
    }
}

// ---- launch ----------------------------------------------------------------
extern "C" void kernel_launch(void* const* d_in, const int* in_sizes, int n_in,
                              void* d_out, int out_size) {
    (void)in_sizes; (void)n_in; (void)out_size;
    const float* x    = (const float*)d_in[0];
    const float* gate = (const float*)d_in[1];
    const float* up   = (const float*)d_in[2];
    const float* down = (const float*)d_in[3];
    float* out = (float*)d_out;

    void *pxc, *pgc, *puc, *pdc, *ph;
    cudaGetSymbolAddress(&pxc, g_xc);
    cudaGetSymbolAddress(&pgc, g_gc);
    cudaGetSymbolAddress(&puc, g_uc);
    cudaGetSymbolAddress(&pdc, g_dc);
    cudaGetSymbolAddress(&ph,  g_h);

    cudaFuncSetAttribute(moe_mma<2, 1>,
                         cudaFuncAttributeMaxDynamicSharedMemorySize, Cfg<2>::SMEM_SZ);
    cudaFuncSetAttribute(moe_mma<1, 0>,
                         cudaFuncAttributeMaxDynamicSharedMemorySize, Cfg<1>::SMEM_SZ);

    // Pre-round operands to tf32 (exact feed-through in the GEMMs).
    const size_t nx4 = (size_t)NTOK * DIMX / 4;
    const size_t nw4 = (size_t)NE * DIMX * HID / 4;
    cvt_tf32<<<8192, 256>>>((const float4*)x,    (float4*)pxc, nx4);
    cvt_tf32<<<8192, 256>>>((const float4*)gate, (float4*)pgc, nw4);
    cvt_tf32<<<8192, 256>>>((const float4*)up,   (float4*)puc, nw4);
    cvt_tf32<<<8192, 256>>>((const float4*)down, (float4*)pdc, nw4);

    // h = silu(x@gate) * (x@up)   (fused, shared A tile)
    moe_mma<2, 1><<<dim3(HID / 128, NTOK / 128), 256, Cfg<2>::SMEM_SZ>>>(
        (const float*)pxc, (const float*)pgc, (const float*)puc,
        (float*)ph, DIMX, HID);
    // out = h @ down
    moe_mma<1, 0><<<dim3(DIMX / 128, NTOK / 128), 256, Cfg<1>::SMEM_SZ>>>(
        (const float*)ph, (const float*)pdc, nullptr, out, HID, DIMX);
}